// round 1
// baseline (speedup 1.0000x reference)
#include <cuda_runtime.h>
#include <math.h>

// Problem constants (match reference)
#define B_DIM 64
#define K_DIM 128
#define H_DIM 64
#define W_DIM 64
#define PLANE (H_DIM * W_DIM)        // 4096
#define N_PLANES (B_DIM * K_DIM)     // 8192
#define N_BOXES 256
#define ALPHA 1.0f
#define BETA 0.5f

__device__ float g_cls_sum;
__device__ float g_loc_sum;

__global__ void zero_accum_kernel() {
    g_cls_sum = 0.0f;
    g_loc_sum = 0.0f;
}

__device__ __forceinline__ float softplus_f(float x) {
    // log(1 + exp(x)) stable
    float ax = fabsf(x);
    return log1pf(expf(-ax)) + fmaxf(x, 0.0f);
}

// One CTA per (b,k) plane: max over 4096 floats, BCE-with-logits, accumulate.
__global__ __launch_bounds__(256) void cls_kernel(const float* __restrict__ cams,
                                                  const float* __restrict__ concepts_gt) {
    int plane = blockIdx.x;
    const float4* p = reinterpret_cast<const float4*>(cams + (size_t)plane * PLANE);

    int t = threadIdx.x;
    float m = -INFINITY;
#pragma unroll
    for (int i = 0; i < 4; i++) {
        float4 v = p[i * 256 + t];
        m = fmaxf(m, fmaxf(fmaxf(v.x, v.y), fmaxf(v.z, v.w)));
    }
    // warp reduce max
#pragma unroll
    for (int off = 16; off > 0; off >>= 1)
        m = fmaxf(m, __shfl_xor_sync(0xFFFFFFFFu, m, off));

    __shared__ float sm[8];
    int wid = t >> 5, lid = t & 31;
    if (lid == 0) sm[wid] = m;
    __syncthreads();
    if (t == 0) {
        float bm = sm[0];
#pragma unroll
        for (int w = 1; w < 8; w++) bm = fmaxf(bm, sm[w]);
        float y = concepts_gt[plane];
        // bce = y*softplus(-z) + (1-y)*softplus(z)
        float bce = y * softplus_f(-bm) + (1.0f - y) * softplus_f(bm);
        atomicAdd(&g_cls_sum, bce);
    }
}

// One CTA per box: sigmoid + masked inside/outside sums.
__global__ __launch_bounds__(256) void loc_kernel(const float* __restrict__ cams,
                                                  const int* __restrict__ box_b,
                                                  const int* __restrict__ box_c,
                                                  const int* __restrict__ y0v,
                                                  const int* __restrict__ y1v,
                                                  const int* __restrict__ x0v,
                                                  const int* __restrict__ x1v) {
    int box = blockIdx.x;
    int b = box_b[box];
    int c = box_c[box];
    int y0 = y0v[box], y1 = y1v[box], x0 = x0v[box], x1 = x1v[box];

    const float4* p = reinterpret_cast<const float4*>(
        cams + ((size_t)b * K_DIM + c) * PLANE);

    int t = threadIdx.x;
    float inside = 0.0f, outside = 0.0f;
#pragma unroll
    for (int i = 0; i < 4; i++) {
        int u = i * 256 + t;            // float4 index within plane [0,1024)
        float4 v = p[u];
        int row = u >> 4;               // 16 float4 per row (W=64)
        int col0 = (u & 15) << 2;
        float vals[4] = {v.x, v.y, v.z, v.w};
        bool rin = (row >= y0) && (row < y1);
#pragma unroll
        for (int j = 0; j < 4; j++) {
            int col = col0 + j;
            float s = 1.0f / (1.0f + expf(-vals[j]));
            bool in = rin && (col >= x0) && (col < x1);
            float d = s - 1.0f;
            if (in) inside += d * d;
            else    outside += s * s;
        }
    }
    // warp reduce sums
#pragma unroll
    for (int off = 16; off > 0; off >>= 1) {
        inside  += __shfl_xor_sync(0xFFFFFFFFu, inside, off);
        outside += __shfl_xor_sync(0xFFFFFFFFu, outside, off);
    }
    __shared__ float si[8], so[8];
    int wid = t >> 5, lid = t & 31;
    if (lid == 0) { si[wid] = inside; so[wid] = outside; }
    __syncthreads();
    if (t == 0) {
        float ti = 0.0f, to = 0.0f;
#pragma unroll
        for (int w = 0; w < 8; w++) { ti += si[w]; to += so[w]; }
        float area = (float)((y1 - y0) * (x1 - x0));
        const float eps = 1e-6f;
        float loss = ti / (area + eps) + to / ((float)PLANE - area + eps);
        atomicAdd(&g_loc_sum, loss);
    }
}

__global__ void finalize_kernel(float* __restrict__ out) {
    out[0] = ALPHA * (g_cls_sum / (float)N_PLANES) + BETA * (g_loc_sum / (float)N_BOXES);
}

extern "C" void kernel_launch(void* const* d_in, const int* in_sizes, int n_in,
                              void* d_out, int out_size) {
    const float* cams        = (const float*)d_in[0];
    const float* concepts_gt = (const float*)d_in[1];
    const int*   box_b       = (const int*)d_in[2];
    const int*   box_c       = (const int*)d_in[3];
    const int*   y0          = (const int*)d_in[4];
    const int*   y1          = (const int*)d_in[5];
    const int*   x0          = (const int*)d_in[6];
    const int*   x1          = (const int*)d_in[7];
    float* out = (float*)d_out;

    zero_accum_kernel<<<1, 1>>>();
    cls_kernel<<<N_PLANES, 256>>>(cams, concepts_gt);
    loc_kernel<<<N_BOXES, 256>>>(cams, box_b, box_c, y0, y1, x0, x1);
    finalize_kernel<<<1, 1>>>(out);
}